// round 12
// baseline (speedup 1.0000x reference)
#include <cuda_runtime.h>
#include <cuda_fp16.h>
#include <cstdint>

#define T_   128
#define B_   64
#define E_   300
#define H_   2048
#define G4   8192
#define TB   8192
#define KP   320
#define KCAT 960

// step-kernel config: warp-specialized pipeline
#define NCTA   128
#define NT     64                 // gate rows per CTA
#define JT     16                 // hidden units per CTA
#define STAGES 4
#define A_BYTES 18432             // 128 rows x 144B
#define B_BYTES 9216              // 64 rows x 144B
#define STAGE_BYTES (A_BYTES + B_BYTES)     // 27648
#define XG_BYTES 32768                      // 128 rows x 256B
#define DYN_SMEM (XG_BYTES + STAGES * STAGE_BYTES)  // 143360 (proven size)
#define NCHUNK 32

// ---------------- scratch ----------------
__device__ __align__(256) __half g_Acat[(size_t)TB * KCAT];
__device__ __align__(256) __half g_Bcat[(size_t)G4 * KCAT];
__device__ __align__(256) __half g_Whh16[(size_t)G4 * H_];   // gate-interleaved rows
__device__ __align__(256) float  g_Xg[(size_t)TB * G4];      // [t*B+b][np] np=4j+g
__device__ __align__(256) float  g_bias[G4];
__device__ __align__(256) float  g_c[128 * H_];              // cell state
__device__ __align__(256) __half g_h16[128 * H_];            // hidden state

// ---------------- helpers ----------------
__device__ __forceinline__ uint32_t smemAddr(const void* p) {
    return (uint32_t)__cvta_generic_to_shared(p);
}
__device__ __forceinline__ void ldsm4(uint32_t r[4], uint32_t addr) {
    asm volatile("ldmatrix.sync.aligned.m8n8.x4.shared.b16 {%0,%1,%2,%3}, [%4];\n"
                 : "=r"(r[0]), "=r"(r[1]), "=r"(r[2]), "=r"(r[3]) : "r"(addr));
}
__device__ __forceinline__ void mma16816(float* c, const uint32_t* a, const uint32_t* b) {
    asm volatile("mma.sync.aligned.m16n8k16.row.col.f32.f16.f16.f32 "
                 "{%0,%1,%2,%3}, {%4,%5,%6,%7}, {%8,%9}, {%0,%1,%2,%3};\n"
                 : "+f"(c[0]), "+f"(c[1]), "+f"(c[2]), "+f"(c[3])
                 : "r"(a[0]), "r"(a[1]), "r"(a[2]), "r"(a[3]), "r"(b[0]), "r"(b[1]));
}
#define CP16(dst, src) asm volatile("cp.async.cg.shared.global [%0], [%1], 16;\n" :: "r"(dst), "l"(src))
#define CP_COMMIT()    asm volatile("cp.async.commit_group;\n" ::: "memory")
#define CP_WAIT(N)     asm volatile("cp.async.wait_group %0;\n" :: "n"(N) : "memory")

#define MBAR_INIT(a, c) asm volatile("mbarrier.init.shared.b64 [%0], %1;" :: "r"((uint32_t)(a)), "r"((uint32_t)(c)) : "memory")
#define MBAR_ARRIVE(a)  asm volatile("mbarrier.arrive.shared.b64 _, [%0];" :: "r"((uint32_t)(a)) : "memory")
#define CP_MBAR_ARRIVE(a) asm volatile("cp.async.mbarrier.arrive.noinc.shared.b64 [%0];" :: "r"((uint32_t)(a)) : "memory")
#define MBAR_WAIT(a, p) do {                                                    \
    asm volatile("{\n\t.reg .pred P1;\n\t"                                      \
        "W%=:\n\t"                                                              \
        "mbarrier.try_wait.parity.shared.b64 P1, [%0], %1;\n\t"                 \
        "@P1 bra.uni D%=;\n\t"                                                  \
        "bra.uni W%=;\n\t"                                                      \
        "D%=:\n\t}" :: "r"((uint32_t)(a)), "r"((uint32_t)(p)) : "memory");      \
} while (0)
#define BARC()  asm volatile("bar.sync 3, 512;" ::: "memory")   // consumers only

__device__ __forceinline__ float sigm(float x) { return 1.f / (1.f + __expf(-x)); }
__device__ __forceinline__ float tanh_f(float x) { return 2.f / (1.f + __expf(-2.f * x)) - 1.f; }

// ---------------- merged prep kernel (block-range dispatch) ----------------
#define NB_WHH  65536     // G4*H/256
#define NB_WIH  10240     // G4*KP/256
#define NB_X    10240     // TB*KP/256
#define NB_MISC 1056      // 1024 (state) + 32 (bias)
__global__ void prep_all(const int* __restrict__ tokens, const float* __restrict__ embed,
                         const float* __restrict__ W_ih, const float* __restrict__ W_hh,
                         const float* __restrict__ b_ih, const float* __restrict__ b_hh)
{
    int blk = blockIdx.x;
    if (blk < NB_WHH) {
        int i = blk * 256 + threadIdx.x;
        int n = i >> 11, k = i & (H_ - 1);
        int np = ((n & (H_ - 1)) << 2) | (n >> 11);
        g_Whh16[(size_t)np * H_ + k] = __float2half(W_hh[i]);
        return;
    }
    blk -= NB_WHH;
    if (blk < NB_WIH) {
        int i = blk * 256 + threadIdx.x;
        int n = i / KP, c = i % KP;
        int np = ((n & (H_ - 1)) << 2) | (n >> 11);
        float w = (c < E_) ? W_ih[n * E_ + c] : 0.f;
        __half hi = __float2half(w);
        __half lo = __float2half(w - __half2float(hi));
        g_Bcat[(size_t)np * KCAT + c]          = hi;
        g_Bcat[(size_t)np * KCAT + KP + c]     = lo;
        g_Bcat[(size_t)np * KCAT + 2 * KP + c] = hi;
        return;
    }
    blk -= NB_WIH;
    if (blk < NB_X) {
        int i = blk * 256 + threadIdx.x;
        int row = i / KP, c = i % KP;
        int tok = tokens[row];
        float v = (c < E_) ? embed[(size_t)tok * E_ + c] : 0.f;
        __half hi = __float2half(v);
        __half lo = __float2half(v - __half2float(hi));
        g_Acat[(size_t)row * KCAT + c]          = hi;
        g_Acat[(size_t)row * KCAT + KP + c]     = hi;
        g_Acat[(size_t)row * KCAT + 2 * KP + c] = lo;
        return;
    }
    blk -= NB_X;
    if (blk < 1024) {
        int i = blk * 256 + threadIdx.x;
        g_c[i] = 0.f;
        g_h16[i] = __float2half(0.f);
        return;
    }
    blk -= 1024;
    {
        int i = blk * 256 + threadIdx.x;
        if (i < G4) g_bias[i] = b_ih[i] + b_hh[i];
    }
}

// ---------------- Xg GEMM (C[M,N]=A@B^T, tile 128x64, runs once) ----------------
__global__ __launch_bounds__(256) void gemm_kernel(
    const __half* __restrict__ A, const __half* __restrict__ B, float* __restrict__ C,
    int lda, int ldb, int ldc, int K)
{
    __shared__ __half As[128][72];
    __shared__ __half Bs[64][72];
    int tid = threadIdx.x, lane = tid & 31, warp = tid >> 5;
    int wm = warp & 3, wn = warp >> 2;
    int m0 = blockIdx.y * 128, n0 = blockIdx.x * 64;

    float acc[2][4][4];
#pragma unroll
    for (int mi = 0; mi < 2; mi++)
#pragma unroll
        for (int ni = 0; ni < 4; ni++)
#pragma unroll
            for (int q = 0; q < 4; q++) acc[mi][ni][q] = 0.f;

    uint32_t asB = smemAddr(As), bsB = smemAddr(Bs);
    uint32_t aRowByte = (uint32_t)(wm * 32 + (lane & 15)) * 144;
    uint32_t aColByte = (uint32_t)((lane >> 4) << 3) * 2;
    uint32_t bRowByte = (uint32_t)(wn * 32 + ((lane >> 4) & 1) * 8 + (lane & 7)) * 144;
    uint32_t bColByte = (uint32_t)(((lane >> 3) & 1) << 3) * 2;

    for (int k0 = 0; k0 < K; k0 += 64) {
#pragma unroll
        for (int i = 0; i < 4; i++) {
            int v = tid + i * 256; int r = v >> 3, cc = (v & 7) << 3;
            *(uint4*)&As[r][cc] = *(const uint4*)&A[(size_t)(m0 + r) * lda + k0 + cc];
        }
#pragma unroll
        for (int i = 0; i < 2; i++) {
            int v = tid + i * 256; int r = v >> 3, cc = (v & 7) << 3;
            *(uint4*)&Bs[r][cc] = *(const uint4*)&B[(size_t)(n0 + r) * ldb + k0 + cc];
        }
        __syncthreads();
#pragma unroll
        for (int ks = 0; ks < 4; ks++) {
            uint32_t a[2][4], b[2][4];
            uint32_t ka = (uint32_t)ks * 32;
            ldsm4(a[0], asB + aRowByte + ka + aColByte);
            ldsm4(a[1], asB + aRowByte + 16u * 144 + ka + aColByte);
            ldsm4(b[0], bsB + bRowByte + ka + bColByte);
            ldsm4(b[1], bsB + bRowByte + 16u * 144 + ka + bColByte);
#pragma unroll
            for (int mi = 0; mi < 2; mi++)
#pragma unroll
                for (int ni = 0; ni < 4; ni++)
                    mma16816(acc[mi][ni], a[mi], &b[ni >> 1][(ni & 1) * 2]);
        }
        __syncthreads();
    }
#pragma unroll
    for (int mi = 0; mi < 2; mi++) {
        int row = m0 + wm * 32 + mi * 16 + (lane >> 2);
#pragma unroll
        for (int ni = 0; ni < 4; ni++) {
            int col = n0 + wn * 32 + ni * 8 + ((lane & 3) << 1);
            float* cp = C + (size_t)row * ldc + col;
            cp[0] = acc[mi][ni][0]; cp[1] = acc[mi][ni][1];
            cp += (size_t)ldc * 8;
            cp[0] = acc[mi][ni][2]; cp[1] = acc[mi][ni][3];
        }
    }
}

// ---------------- fused LSTM step kernel (warp-specialized) ----------------
// 128 CTAs x 640 thr. Warps 0-15: consumers (warp tile 16x32, full 128x64
// tile, acc over 32 chunks). Warps 16-19: producers (cp.async loaders).
// 4-stage mbarrier pipeline, NO bar.sync/wait_group in the mainloop.
__global__ __launch_bounds__(640, 1) void lstm_step(
    int s, const int* __restrict__ lens, float* __restrict__ out)
{
    extern __shared__ char dsm[];
    __shared__ float Cs[128][68];
    __shared__ float sBias[NT];
    __shared__ __align__(8) uint64_t sMbar[8];   // full[0..3], empty[0..3]

    const int tid = threadIdx.x, lane = tid & 31, warp = tid >> 5;
    const int cta = blockIdx.x;
    const int n0 = cta * NT;
    const int j0 = cta * JT;

    const uint32_t dynB = smemAddr(dsm);
    const uint32_t xgB  = dynB;                  // Xg at offset 0
    const uint32_t stB  = dynB + XG_BYTES;       // 4 pipeline stages
    const uint32_t fullB  = smemAddr(&sMbar[0]);
    const uint32_t emptyB = smemAddr(&sMbar[4]);

    if (tid == 0) {
#pragma unroll
        for (int i = 0; i < STAGES; i++) {
            MBAR_INIT(fullB + 8 * i, 128);   // producer threads
            MBAR_INIT(emptyB + 8 * i, 16);   // one per consumer warp
        }
    }
    if (tid < NT) sBias[tid] = g_bias[(tid & 3) * H_ + j0 + (tid >> 2)];
    __syncthreads();

    if (warp >= 16) {
        // ================= producers (128 threads) =================
        const int ptid = tid - 512;
        uint32_t dst[12]; const __half* src[12];
#pragma unroll
        for (int i = 0; i < 12; i++) {
            int u = ptid + i * 128;          // 0..1535
            if (u < 1024) {                  // A: 128 rows x 8 segs
                int r = u >> 3, sg = u & 7;
                dst[i] = (uint32_t)(r * 144 + sg * 16);
                src[i] = g_h16 + (size_t)r * H_ + sg * 8;
            } else {                         // B: 64 rows x 8 segs
                int v = u - 1024;
                int r = v >> 3, sg = v & 7;
                dst[i] = (uint32_t)(A_BYTES + r * 144 + sg * 16);
                src[i] = g_Whh16 + (size_t)(n0 + r) * H_ + sg * 8;
            }
        }
        for (int ck = 0; ck < NCHUNK; ck++) {
            int st = ck & 3, m = ck >> 2;
            if (m > 0) MBAR_WAIT(emptyB + 8 * st, (m - 1) & 1);
            uint32_t base = stB + (uint32_t)st * STAGE_BYTES;
#pragma unroll
            for (int i = 0; i < 12; i++) CP16(base + dst[i], src[i] + ck * 64);
            CP_MBAR_ARRIVE(fullB + 8 * st);
        }
    } else {
        // ================= consumers (512 threads) =================
        // Xg prefetch through this thread's own cp.async group
#pragma unroll
        for (int k = 0; k < 4; k++) {
            int u = tid * 4 + k;                 // 16B unit
            int row = u >> 4, seg = u & 15;
            int rb = row & 63;
            int rt = (row < 64) ? s : (T_ - 1 - s);
            const float* srcx = g_Xg + (size_t)(rt * B_ + rb) * G4 + 4 * j0 + seg * 4;
            CP16(xgB + (uint32_t)u * 16, srcx);
        }
        CP_COMMIT();

        const int wm = warp & 7;          // m16 block
        const int wn = warp >> 3;         // n32 half
        const uint32_t aRowByte = (uint32_t)(wm * 16 + (lane & 15)) * 144;
        const uint32_t aColByte = (uint32_t)((lane >> 4) << 3) * 2;
        const uint32_t bRowByte0 = (uint32_t)(wn * 32 + ((lane >> 4) & 1) * 8 + (lane & 7)) * 144;
        const uint32_t bColByte  = (uint32_t)(((lane >> 3) & 1) << 3) * 2;

        float acc[4][4];
#pragma unroll
        for (int ni = 0; ni < 4; ni++)
#pragma unroll
            for (int q = 0; q < 4; q++) acc[ni][q] = 0.f;

        for (int ck = 0; ck < NCHUNK; ck++) {
            int st = ck & 3;
            MBAR_WAIT(fullB + 8 * st, (ck >> 2) & 1);
            uint32_t asB = stB + (uint32_t)st * STAGE_BYTES;
            uint32_t bsB = asB + A_BYTES;
#pragma unroll
            for (int ks = 0; ks < 4; ks++) {
                uint32_t a[4], b[2][4];
                uint32_t ka = (uint32_t)ks * 32;
                ldsm4(a, asB + aRowByte + ka + aColByte);
                ldsm4(b[0], bsB + bRowByte0 + ka + bColByte);
                ldsm4(b[1], bsB + bRowByte0 + 16u * 144 + ka + bColByte);
#pragma unroll
                for (int ni = 0; ni < 4; ni++)
                    mma16816(acc[ni], a, &b[ni >> 1][(ni & 1) * 2]);
            }
            __syncwarp();
            if (lane == 0) MBAR_ARRIVE(emptyB + 8 * st);
        }

        // acc -> smem C (consumer-only named barrier)
        {
            int row = wm * 16 + (lane >> 2);
#pragma unroll
            for (int ni = 0; ni < 4; ni++) {
                int col = wn * 32 + ni * 8 + ((lane & 3) << 1);
                Cs[row][col]     = acc[ni][0];
                Cs[row][col + 1] = acc[ni][1];
                Cs[row + 8][col]     = acc[ni][2];
                Cs[row + 8][col + 1] = acc[ni][3];
            }
        }
        CP_WAIT(0);          // Xg arrived (long ago)
        BARC();

        // -------- fused pointwise: thread -> 4 hidden units of batch row pm --------
        const int pm = tid & 127;
        const int pq = tid >> 7;             // quarter (0..3)
        const int pb = pm & 63;
        const int myLen = lens[pb];
        const float* xg = (const float*)(dsm) + pm * 64 + pq * 16;
        float* cptr = g_c + (size_t)pm * H_ + j0 + pq * 4;
        float4 c0 = *(const float4*)(cptr);
        float cst[4] = {c0.x, c0.y, c0.z, c0.w};

        __half hv4[4];
#pragma unroll
        for (int q = 0; q < 4; q++) {
            int jl = pq * 4 + q, nl = 4 * jl;
            float4 z  = *(const float4*)&Cs[pm][nl];
            float4 x4 = *(const float4*)(xg + 4 * q);
            float zi = z.x + x4.x + sBias[nl + 0];
            float zf = z.y + x4.y + sBias[nl + 1];
            float zg = z.z + x4.z + sBias[nl + 2];
            float zo = z.w + x4.w + sBias[nl + 3];
            float cv = sigm(zf) * cst[q] + sigm(zi) * tanh_f(zg);
            float hv = sigm(zo) * tanh_f(cv);
            cst[q] = cv;
            hv4[q] = __float2half(hv);
            if (pm < 64) {
                if (myLen == s + 1) out[(size_t)pb * (2 * H_) + j0 + jl] = hv;
            } else if (s == T_ - 1) {
                out[(size_t)pb * (2 * H_) + H_ + j0 + jl] = hv;
            }
        }
        *(float4*)(cptr) = make_float4(cst[0], cst[1], cst[2], cst[3]);
        *(uint2*)&g_h16[(size_t)pm * H_ + j0 + pq * 4] = *(uint2*)hv4;
    }
}

// ---------------- launch ----------------
extern "C" void kernel_launch(void* const* d_in, const int* in_sizes, int n_in,
                              void* d_out, int out_size)
{
    (void)in_sizes; (void)n_in; (void)out_size;
    const int*   tokens = (const int*)  d_in[0];
    const int*   lens   = (const int*)  d_in[1];
    const float* embed  = (const float*)d_in[2];
    const float* W_ih   = (const float*)d_in[3];
    const float* W_hh   = (const float*)d_in[4];
    const float* b_ih   = (const float*)d_in[5];
    const float* b_hh   = (const float*)d_in[6];
    float* out = (float*)d_out;

    cudaFuncSetAttribute(lstm_step,
                         cudaFuncAttributeMaxDynamicSharedMemorySize, DYN_SMEM);

    void *pA, *pB, *pXg;
    cudaGetSymbolAddress(&pA, g_Acat);
    cudaGetSymbolAddress(&pB, g_Bcat);
    cudaGetSymbolAddress(&pXg, g_Xg);

    prep_all<<<NB_WHH + NB_WIH + NB_X + NB_MISC, 256>>>(
        tokens, embed, W_ih, W_hh, b_ih, b_hh);

    gemm_kernel<<<dim3(G4 / 64, TB / 128), 256>>>(
        (const __half*)pA, (const __half*)pB, (float*)pXg, KCAT, KCAT, G4, KCAT);

    for (int s = 0; s < T_; s++)
        lstm_step<<<NCTA, 640, DYN_SMEM>>>(s, lens, out);
}

// round 14
// speedup vs baseline: 1.0788x; 1.0788x over previous
#include <cuda_runtime.h>
#include <cuda_fp16.h>
#include <cstdint>

#define T_   128
#define B_   64
#define E_   300
#define H_   2048
#define G4   8192
#define TB   8192
#define KP   320
#define KCAT 960

// step-kernel config: two K-groups x 4 warps, warp tile 64x32
#define NCTA   128
#define NT     64                 // gate rows per CTA
#define JT     16                 // hidden units per CTA
#define A_BYTES 18432             // 128 rows x 144B
#define B_BYTES 9216              // 64 rows x 144B
#define STAGE_BYTES (A_BYTES + B_BYTES)     // 27648
#define XG_BYTES 32768                      // 128 rows x 256B
#define DYN_SMEM (XG_BYTES + 4 * STAGE_BYTES)  // 143360 (proven size)
#define KHALF  1024               // K per group
#define NCHUNK 16                 // K64 chunks per group

// ---------------- scratch ----------------
__device__ __align__(256) __half g_Acat[(size_t)TB * KCAT];
__device__ __align__(256) __half g_Bcat[(size_t)G4 * KCAT];
__device__ __align__(256) __half g_Whh16[(size_t)G4 * H_];   // gate-interleaved rows
__device__ __align__(256) float  g_Xg[(size_t)TB * G4];      // [t*B+b][np] np=4j+g
__device__ __align__(256) float  g_bias[G4];
__device__ __align__(256) float  g_c[128 * H_];              // cell state
__device__ __align__(256) __half g_h16[128 * H_];            // hidden state

// ---------------- helpers ----------------
__device__ __forceinline__ uint32_t smemAddr(const void* p) {
    return (uint32_t)__cvta_generic_to_shared(p);
}
__device__ __forceinline__ void ldsm4(uint32_t r[4], uint32_t addr) {
    asm volatile("ldmatrix.sync.aligned.m8n8.x4.shared.b16 {%0,%1,%2,%3}, [%4];\n"
                 : "=r"(r[0]), "=r"(r[1]), "=r"(r[2]), "=r"(r[3]) : "r"(addr));
}
__device__ __forceinline__ void mma16816(float* c, const uint32_t* a, const uint32_t* b) {
    asm volatile("mma.sync.aligned.m16n8k16.row.col.f32.f16.f16.f32 "
                 "{%0,%1,%2,%3}, {%4,%5,%6,%7}, {%8,%9}, {%0,%1,%2,%3};\n"
                 : "+f"(c[0]), "+f"(c[1]), "+f"(c[2]), "+f"(c[3])
                 : "r"(a[0]), "r"(a[1]), "r"(a[2]), "r"(a[3]), "r"(b[0]), "r"(b[1]));
}
#define CP16(dst, src) asm volatile("cp.async.cg.shared.global [%0], [%1], 16;\n" :: "r"(dst), "l"(src))
#define CP_COMMIT()    asm volatile("cp.async.commit_group;\n" ::: "memory")
#define CP_WAIT(N)     asm volatile("cp.async.wait_group %0;\n" :: "n"(N) : "memory")
#define BARG(id)       asm volatile("bar.sync %0, %1;" :: "r"(id), "r"(128) : "memory")

__device__ __forceinline__ float sigm(float x) { return 1.f / (1.f + __expf(-x)); }
__device__ __forceinline__ float tanh_f(float x) { return 2.f / (1.f + __expf(-2.f * x)) - 1.f; }

// ---------------- merged prep kernel (block-range dispatch) ----------------
#define NB_WHH  65536     // G4*H/256
#define NB_WIH  10240     // G4*KP/256
#define NB_X    10240     // TB*KP/256
#define NB_MISC 1056      // 1024 (state) + 32 (bias)
__global__ void prep_all(const int* __restrict__ tokens, const float* __restrict__ embed,
                         const float* __restrict__ W_ih, const float* __restrict__ W_hh,
                         const float* __restrict__ b_ih, const float* __restrict__ b_hh)
{
    int blk = blockIdx.x;
    if (blk < NB_WHH) {
        int i = blk * 256 + threadIdx.x;
        int n = i >> 11, k = i & (H_ - 1);
        int np = ((n & (H_ - 1)) << 2) | (n >> 11);
        g_Whh16[(size_t)np * H_ + k] = __float2half(W_hh[i]);
        return;
    }
    blk -= NB_WHH;
    if (blk < NB_WIH) {
        int i = blk * 256 + threadIdx.x;
        int n = i / KP, c = i % KP;
        int np = ((n & (H_ - 1)) << 2) | (n >> 11);
        float w = (c < E_) ? W_ih[n * E_ + c] : 0.f;
        __half hi = __float2half(w);
        __half lo = __float2half(w - __half2float(hi));
        g_Bcat[(size_t)np * KCAT + c]          = hi;
        g_Bcat[(size_t)np * KCAT + KP + c]     = lo;
        g_Bcat[(size_t)np * KCAT + 2 * KP + c] = hi;
        return;
    }
    blk -= NB_WIH;
    if (blk < NB_X) {
        int i = blk * 256 + threadIdx.x;
        int row = i / KP, c = i % KP;
        int tok = tokens[row];
        float v = (c < E_) ? embed[(size_t)tok * E_ + c] : 0.f;
        __half hi = __float2half(v);
        __half lo = __float2half(v - __half2float(hi));
        g_Acat[(size_t)row * KCAT + c]          = hi;
        g_Acat[(size_t)row * KCAT + KP + c]     = hi;
        g_Acat[(size_t)row * KCAT + 2 * KP + c] = lo;
        return;
    }
    blk -= NB_X;
    if (blk < 1024) {
        int i = blk * 256 + threadIdx.x;
        g_c[i] = 0.f;
        g_h16[i] = __float2half(0.f);
        return;
    }
    blk -= 1024;
    {
        int i = blk * 256 + threadIdx.x;
        if (i < G4) g_bias[i] = b_ih[i] + b_hh[i];
    }
}

// ---------------- Xg GEMM (C[M,N]=A@B^T, tile 128x64, runs once) ----------------
__global__ __launch_bounds__(256) void gemm_kernel(
    const __half* __restrict__ A, const __half* __restrict__ B, float* __restrict__ C,
    int lda, int ldb, int ldc, int K)
{
    __shared__ __half As[128][72];
    __shared__ __half Bs[64][72];
    int tid = threadIdx.x, lane = tid & 31, warp = tid >> 5;
    int wm = warp & 3, wn = warp >> 2;
    int m0 = blockIdx.y * 128, n0 = blockIdx.x * 64;

    float acc[2][4][4];
#pragma unroll
    for (int mi = 0; mi < 2; mi++)
#pragma unroll
        for (int ni = 0; ni < 4; ni++)
#pragma unroll
            for (int q = 0; q < 4; q++) acc[mi][ni][q] = 0.f;

    uint32_t asB = smemAddr(As), bsB = smemAddr(Bs);
    uint32_t aRowByte = (uint32_t)(wm * 32 + (lane & 15)) * 144;
    uint32_t aColByte = (uint32_t)((lane >> 4) << 3) * 2;
    uint32_t bRowByte = (uint32_t)(wn * 32 + ((lane >> 4) & 1) * 8 + (lane & 7)) * 144;
    uint32_t bColByte = (uint32_t)(((lane >> 3) & 1) << 3) * 2;

    for (int k0 = 0; k0 < K; k0 += 64) {
#pragma unroll
        for (int i = 0; i < 4; i++) {
            int v = tid + i * 256; int r = v >> 3, cc = (v & 7) << 3;
            *(uint4*)&As[r][cc] = *(const uint4*)&A[(size_t)(m0 + r) * lda + k0 + cc];
        }
#pragma unroll
        for (int i = 0; i < 2; i++) {
            int v = tid + i * 256; int r = v >> 3, cc = (v & 7) << 3;
            *(uint4*)&Bs[r][cc] = *(const uint4*)&B[(size_t)(n0 + r) * ldb + k0 + cc];
        }
        __syncthreads();
#pragma unroll
        for (int ks = 0; ks < 4; ks++) {
            uint32_t a[2][4], b[2][4];
            uint32_t ka = (uint32_t)ks * 32;
            ldsm4(a[0], asB + aRowByte + ka + aColByte);
            ldsm4(a[1], asB + aRowByte + 16u * 144 + ka + aColByte);
            ldsm4(b[0], bsB + bRowByte + ka + bColByte);
            ldsm4(b[1], bsB + bRowByte + 16u * 144 + ka + bColByte);
#pragma unroll
            for (int mi = 0; mi < 2; mi++)
#pragma unroll
                for (int ni = 0; ni < 4; ni++)
                    mma16816(acc[mi][ni], a[mi], &b[ni >> 1][(ni & 1) * 2]);
        }
        __syncthreads();
    }
#pragma unroll
    for (int mi = 0; mi < 2; mi++) {
        int row = m0 + wm * 32 + mi * 16 + (lane >> 2);
#pragma unroll
        for (int ni = 0; ni < 4; ni++) {
            int col = n0 + wn * 32 + ni * 8 + ((lane & 3) << 1);
            float* cp = C + (size_t)row * ldc + col;
            cp[0] = acc[mi][ni][0]; cp[1] = acc[mi][ni][1];
            cp += (size_t)ldc * 8;
            cp[0] = acc[mi][ni][2]; cp[1] = acc[mi][ni][3];
        }
    }
}

// ---------------- fused LSTM step kernel ----------------
// 128 CTAs x 256 thr. Warps 0-3 = group 0 (K[0,1024)), warps 4-7 = group 1.
// Warp tile 64x32 (2 along M x 2 along N per group). Per chunk: ldsm all
// fragments -> group barrier -> issue next cp.async -> mma (overlapped).
__global__ __launch_bounds__(256, 1) void lstm_step(
    int s, const int* __restrict__ lens, float* __restrict__ out)
{
    extern __shared__ char dsm[];
    __shared__ float Cs[128][68];
    __shared__ float sBias[NT];

    const int tid = threadIdx.x, lane = tid & 31;
    const int g    = tid >> 7;           // K-group 0/1
    const int gtid = tid & 127;
    const int gwarp = gtid >> 5;         // 0..3 within group
    const int wm = gwarp & 1;            // 2 along M (64 rows each)
    const int wn = gwarp >> 1;           // 2 along N (32 cols each)
    const int cta = blockIdx.x;
    const int n0 = cta * NT;
    const int j0 = cta * JT;
    const int barId = 1 + g;

    const uint32_t dynB = smemAddr(dsm);
    const uint32_t xgB  = dynB;                       // Xg at offset 0
    const uint32_t stB  = dynB + XG_BYTES + (uint32_t)g * 2 * STAGE_BYTES;

    if (tid < NT) sBias[tid] = g_bias[(tid & 3) * H_ + j0 + (tid >> 2)];

    // ---- commit 1 (all threads): prefetch Xg slice (128 rows x 256B) ----
#pragma unroll
    for (int k = 0; k < 8; k++) {
        int u = tid * 8 + k;                 // 16B unit, 2048 total
        int row = u >> 4, seg = u & 15;
        int rb = row & 63;
        int rt = (row < 64) ? s : (T_ - 1 - s);
        const float* src = g_Xg + (size_t)(rt * B_ + rb) * G4 + 4 * j0 + seg * 4;
        CP16(xgB + (uint32_t)u * 16, src);
    }
    CP_COMMIT();

    // loader offsets (per group, 128 threads: A 8 units/thr, B 4 units/thr)
    uint32_t aDst[8]; const __half* aSrc[8];
#pragma unroll
    for (int i = 0; i < 8; i++) {
        int v = gtid + i * 128, r = v >> 3, sg = v & 7;
        aDst[i] = (uint32_t)(r * 144 + sg * 16);
        aSrc[i] = g_h16 + (size_t)r * H_ + g * KHALF + sg * 8;
    }
    uint32_t bDst[4]; const __half* bSrc[4];
#pragma unroll
    for (int i = 0; i < 4; i++) {
        int v = gtid + i * 128, r = v >> 3, sg = v & 7;
        bDst[i] = (uint32_t)(r * 144 + sg * 16);
        bSrc[i] = g_Whh16 + (size_t)(n0 + r) * H_ + g * KHALF + sg * 8;
    }

    // ldsm addressing (within a stage)
    const uint32_t aRowByte = (uint32_t)(wm * 64 + (lane & 15)) * 144;
    const uint32_t aColByte = (uint32_t)((lane >> 4) << 3) * 2;
    const uint32_t bRowByte = (uint32_t)(wn * 32 + ((lane >> 4) & 1) * 8 + (lane & 7)) * 144;
    const uint32_t bColByte = (uint32_t)(((lane >> 3) & 1) << 3) * 2;

    float acc[4][4][4];    // [mi][ni][q], warp tile 64x32
#pragma unroll
    for (int mi = 0; mi < 4; mi++)
#pragma unroll
        for (int ni = 0; ni < 4; ni++)
#pragma unroll
            for (int q = 0; q < 4; q++) acc[mi][ni][q] = 0.f;

    // prologue: chunks 0,1 -> stages 0,1
#pragma unroll
    for (int p = 0; p < 2; p++) {
        uint32_t aB = stB + p * STAGE_BYTES, bB = aB + A_BYTES;
#pragma unroll
        for (int i = 0; i < 8; i++) CP16(aB + aDst[i], aSrc[i] + p * 64);
#pragma unroll
        for (int i = 0; i < 4; i++) CP16(bB + bDst[i], bSrc[i] + p * 64);
        CP_COMMIT();
    }

    // -------- mainloop: 16 chunks, group-local barriers only --------
    for (int ck = 0; ck < NCHUNK; ck++) {
        if (ck < NCHUNK - 1) CP_WAIT(1); else CP_WAIT(0);
        BARG(barId);
        uint32_t asB = stB + (ck & 1) * STAGE_BYTES;
        uint32_t bsB = asB + A_BYTES;
        // load ALL fragments of this chunk to registers
        uint32_t a[4][4][4], b[4][2][4];   // [ks][mi][4] / [ks][half][4]
#pragma unroll
        for (int ks = 0; ks < 4; ks++) {
            uint32_t ka = (uint32_t)ks * 32;
#pragma unroll
            for (int mi = 0; mi < 4; mi++)
                ldsm4(a[ks][mi], asB + aRowByte + (uint32_t)mi * 2304 + ka + aColByte);
            ldsm4(b[ks][0], bsB + bRowByte + ka + bColByte);
            ldsm4(b[ks][1], bsB + bRowByte + 2304u + ka + bColByte);
        }
        BARG(barId);
        // stage free: issue loads for ck+2 NOW (overlaps with mma below)
        if (ck + 2 < NCHUNK) {
            uint32_t aB = stB + (ck & 1) * STAGE_BYTES, bB = aB + A_BYTES;
#pragma unroll
            for (int i = 0; i < 8; i++) CP16(aB + aDst[i], aSrc[i] + (ck + 2) * 64);
#pragma unroll
            for (int i = 0; i < 4; i++) CP16(bB + bDst[i], bSrc[i] + (ck + 2) * 64);
            CP_COMMIT();
        }
        // 64 mmas from registers
#pragma unroll
        for (int ks = 0; ks < 4; ks++)
#pragma unroll
            for (int mi = 0; mi < 4; mi++)
#pragma unroll
                for (int ni = 0; ni < 4; ni++)
                    mma16816(acc[mi][ni], a[ks][mi], &b[ks][ni >> 1][(ni & 1) * 2]);
    }

    // -------- reduce the two K-halves through Cs --------
    if (g == 0) {
#pragma unroll
        for (int mi = 0; mi < 4; mi++) {
            int row = wm * 64 + mi * 16 + (lane >> 2);
#pragma unroll
            for (int ni = 0; ni < 4; ni++) {
                int col = wn * 32 + ni * 8 + ((lane & 3) << 1);
                Cs[row][col]     = acc[mi][ni][0];
                Cs[row][col + 1] = acc[mi][ni][1];
                Cs[row + 8][col]     = acc[mi][ni][2];
                Cs[row + 8][col + 1] = acc[mi][ni][3];
            }
        }
    }
    __syncthreads();
    if (g == 1) {
#pragma unroll
        for (int mi = 0; mi < 4; mi++) {
            int row = wm * 64 + mi * 16 + (lane >> 2);
#pragma unroll
            for (int ni = 0; ni < 4; ni++) {
                int col = wn * 32 + ni * 8 + ((lane & 3) << 1);
                Cs[row][col]     += acc[mi][ni][0];
                Cs[row][col + 1] += acc[mi][ni][1];
                Cs[row + 8][col]     += acc[mi][ni][2];
                Cs[row + 8][col + 1] += acc[mi][ni][3];
            }
        }
    }
    __syncthreads();

    // -------- fused pointwise: thread -> 8 hidden units of batch row pm --------
    const int pm = tid & 127;
    const int ph = tid >> 7;             // half (0..1): units ph*8..ph*8+7
    const int pb = pm & 63;
    const int myLen = lens[pb];
    const float* xg = (const float*)(dsm) + pm * 64 + ph * 32;
    float* cptr = g_c + (size_t)pm * H_ + j0 + ph * 8;
    float4 c0 = *(const float4*)(cptr);
    float4 c1 = *(const float4*)(cptr + 4);
    float cst[8] = {c0.x, c0.y, c0.z, c0.w, c1.x, c1.y, c1.z, c1.w};

    __half hv8[8];
#pragma unroll
    for (int q = 0; q < 8; q++) {
        int jl = ph * 8 + q, nl = 4 * jl;
        float4 z  = *(const float4*)&Cs[pm][nl];
        float4 x4 = *(const float4*)(xg + 4 * q);
        float zi = z.x + x4.x + sBias[nl + 0];
        float zf = z.y + x4.y + sBias[nl + 1];
        float zg = z.z + x4.z + sBias[nl + 2];
        float zo = z.w + x4.w + sBias[nl + 3];
        float cv = sigm(zf) * cst[q] + sigm(zi) * tanh_f(zg);
        float hv = sigm(zo) * tanh_f(cv);
        cst[q] = cv;
        hv8[q] = __float2half(hv);
        if (pm < 64) {
            if (myLen == s + 1) out[(size_t)pb * (2 * H_) + j0 + jl] = hv;
        } else if (s == T_ - 1) {
            out[(size_t)pb * (2 * H_) + H_ + j0 + jl] = hv;
        }
    }
    *(float4*)(cptr)     = make_float4(cst[0], cst[1], cst[2], cst[3]);
    *(float4*)(cptr + 4) = make_float4(cst[4], cst[5], cst[6], cst[7]);
    *(uint4*)&g_h16[(size_t)pm * H_ + j0 + ph * 8] = *(uint4*)hv8;
}

// ---------------- launch ----------------
extern "C" void kernel_launch(void* const* d_in, const int* in_sizes, int n_in,
                              void* d_out, int out_size)
{
    (void)in_sizes; (void)n_in; (void)out_size;
    const int*   tokens = (const int*)  d_in[0];
    const int*   lens   = (const int*)  d_in[1];
    const float* embed  = (const float*)d_in[2];
    const float* W_ih   = (const float*)d_in[3];
    const float* W_hh   = (const float*)d_in[4];
    const float* b_ih   = (const float*)d_in[5];
    const float* b_hh   = (const float*)d_in[6];
    float* out = (float*)d_out;

    cudaFuncSetAttribute(lstm_step,
                         cudaFuncAttributeMaxDynamicSharedMemorySize, DYN_SMEM);

    void *pA, *pB, *pXg;
    cudaGetSymbolAddress(&pA, g_Acat);
    cudaGetSymbolAddress(&pB, g_Bcat);
    cudaGetSymbolAddress(&pXg, g_Xg);

    prep_all<<<NB_WHH + NB_WIH + NB_X + NB_MISC, 256>>>(
        tokens, embed, W_ih, W_hh, b_ih, b_hh);

    gemm_kernel<<<dim3(G4 / 64, TB / 128), 256>>>(
        (const __half*)pA, (const __half*)pB, (float*)pXg, KCAT, KCAT, G4, KCAT);

    for (int s = 0; s < T_; s++)
        lstm_step<<<NCTA, 256, DYN_SMEM>>>(s, lens, out);
}